// round 8
// baseline (speedup 1.0000x reference)
#include <cuda_runtime.h>
#include <cstdint>

#define U_CNT 100000
#define I_CNT 50000
#define DIM   64
#define N_CNT 150000
#define NNZ_E 1000000
#define SORT_MAX (NNZ_E + 3 * N_CNT)     // padded capacity: 1,450,000

#define SCAN_B 1024
#define NBLK   ((N_CNT + SCAN_B - 1) / SCAN_B)   // 147

// ---- static device scratch (no runtime allocation) ----
__device__ int  g_rowptr_a[N_CNT + 1];    // counts (hist) -> padded exclusive prefix (scan)
__device__ int  g_rowptr_r[N_CNT + 1];
__device__ int  g_rank_a[NNZ_E];          // edge rank within its row (from hist)
__device__ int  g_rank_r[NNZ_E];
__device__ unsigned int g_tile_a[NBLK];   // decoupled-lookback: (value<<2)|status
__device__ unsigned int g_tile_r[NBLK];   // status: 0 invalid, 1 aggregate, 2 prefix
__device__ int2 g_sorted_a[SORT_MAX];     // (col, val bits) grouped by row, 4-padded
__device__ int2 g_sorted_r[SORT_MAX];

static __device__ __forceinline__ const float4* ego_row(
    const float* __restrict__ ue, const float* __restrict__ ie, int n) {
    return (n < U_CNT)
        ? reinterpret_cast<const float4*>(ue + (size_t)n * DIM)
        : reinterpret_cast<const float4*>(ie + (size_t)(n - U_CNT) * DIM);
}

static __device__ __forceinline__ void fma4(float4& acc, float v, const float4& x) {
    acc.x = fmaf(v, x.x, acc.x);
    acc.y = fmaf(v, x.y, acc.y);
    acc.z = fmaf(v, x.z, acc.z);
    acc.w = fmaf(v, x.w, acc.w);
}

// K0: zero counters + lookback state (each graph replay must start clean).
__global__ void lgcn_zero() {
    int i = blockIdx.x * blockDim.x + threadIdx.x;
    if (i < N_CNT) { g_rowptr_a[i] = 0; g_rowptr_r[i] = 0; }
    if (i < NBLK)  { g_tile_a[i] = 0u;  g_tile_r[i] = 0u; }
}

// K1: row histogram; the atomic's return value IS the edge's rank in its row.
__global__ void lgcn_hist(const int* __restrict__ a_rows,
                          const int* __restrict__ r_rows) {
    int i = blockIdx.x * blockDim.x + threadIdx.x;
    if (i < NNZ_E) {
        g_rank_a[i] = atomicAdd(&g_rowptr_a[__ldg(&a_rows[i])], 1);
        g_rank_r[i] = atomicAdd(&g_rowptr_r[__ldg(&r_rows[i])], 1);
    }
}

// K2: single-pass exclusive scan over 4-PADDED counts (decoupled lookback),
// and fill the pad slots of g_sorted with (col=0, val=0) sentinels.
__global__ void lgcn_scan() {
    int  m = blockIdx.y;
    int  b = blockIdx.x;
    int  t = threadIdx.x;
    int*  cnt    = m ? g_rowptr_r : g_rowptr_a;
    int2* sorted = m ? g_sorted_r : g_sorted_a;
    unsigned int* st = m ? g_tile_r : g_tile_a;

    __shared__ int s[SCAN_B];
    __shared__ int ex_prefix;

    int i = b * SCAN_B + t;
    int c = (i < N_CNT) ? cnt[i] : 0;      // raw degree
    int p = (c + 3) & ~3;                  // padded degree
    s[t] = p;
    __syncthreads();
    #pragma unroll
    for (int off = 1; off < SCAN_B; off <<= 1) {
        int u = (t >= off) ? s[t - off] : 0;
        __syncthreads();
        s[t] += u;
        __syncthreads();
    }
    int incl  = s[t];
    int total = s[SCAN_B - 1];

    if (t == 0) {
        if (b == 0) {
            ex_prefix = 0;
            atomicExch(&st[0], ((unsigned int)total << 2) | 2u);
        } else {
            atomicExch(&st[b], ((unsigned int)total << 2) | 1u);
            int run = 0;
            for (int j = b - 1; j >= 0; j--) {
                unsigned int x;
                do { x = atomicAdd(&st[j], 0u); } while ((x & 3u) == 0u);
                run += (int)(x >> 2);
                if ((x & 3u) == 2u) break;
            }
            ex_prefix = run;
            atomicExch(&st[b], ((unsigned int)(run + total) << 2) | 2u);
        }
    }
    __syncthreads();

    if (i < N_CNT) {
        int pref = ex_prefix + incl - p;   // padded exclusive prefix
        cnt[i] = pref;
        int2 z = make_int2(0, 0);
        for (int j = pref + c; j < pref + p; j++) sorted[j] = z;  // <=3 fills
    }
    if (b == NBLK - 1 && t == SCAN_B - 1) cnt[N_CNT] = ex_prefix + incl;
}

// K3: atomic-free scatter — position = rowptr[row] + rank (rank from hist).
__global__ void lgcn_scatter(const int*  __restrict__ a_rows,
                             const int*  __restrict__ a_cols,
                             const float* __restrict__ a_vals,
                             const int*  __restrict__ r_rows,
                             const int*  __restrict__ r_cols,
                             const float* __restrict__ r_vals) {
    int i = blockIdx.x * blockDim.x + threadIdx.x;
    if (i >= NNZ_E) return;
    {
        int row = __ldg(&a_rows[i]);
        int pos = __ldg(&g_rowptr_a[row]) + g_rank_a[i];
        g_sorted_a[pos] = make_int2(__ldg(&a_cols[i]),
                                    __float_as_int(__ldg(&a_vals[i])));
    }
    {
        int row = __ldg(&r_rows[i]);
        int pos = __ldg(&g_rowptr_r[row]) + g_rank_r[i];
        g_sorted_r[pos] = make_int2(__ldg(&r_cols[i]),
                                    __float_as_int(__ldg(&r_vals[i])));
    }
}

// Branchless unroll-4 CSR row reduction (rows are padded to multiples of 4).
static __device__ __forceinline__ float4 row_reduce(
    const int2* __restrict__ sorted, int s, int e, int q,
    const float* __restrict__ ue, const float* __restrict__ ie) {
    float4 acc = make_float4(0.f, 0.f, 0.f, 0.f);
    for (int i = s; i < e; i += 4) {
        int2 c0 = __ldg(&sorted[i]);
        int2 c1 = __ldg(&sorted[i + 1]);
        int2 c2 = __ldg(&sorted[i + 2]);
        int2 c3 = __ldg(&sorted[i + 3]);
        float4 x0 = __ldg(&ego_row(ue, ie, c0.x)[q]);
        float4 x1 = __ldg(&ego_row(ue, ie, c1.x)[q]);
        float4 x2 = __ldg(&ego_row(ue, ie, c2.x)[q]);
        float4 x3 = __ldg(&ego_row(ue, ie, c3.x)[q]);
        fma4(acc, __int_as_float(c0.y), x0);
        fma4(acc, __int_as_float(c1.y), x1);
        fma4(acc, __int_as_float(c2.y), x2);
        fma4(acc, __int_as_float(c3.y), x3);
    }
    return acc;
}

// K4: per-row gather SpMM + full output emit. Streaming stores (never re-read).
__global__ void lgcn_gather(const float* __restrict__ ue,
                            const float* __restrict__ ie,
                            float* __restrict__ out) {
    int idx = blockIdx.x * blockDim.x + threadIdx.x;
    if (idx >= N_CNT * 16) return;
    int n = idx >> 4;
    int q = idx & 15;

    float4 e = __ldg(&ego_row(ue, ie, n)[q]);

    int s0 = __ldg(&g_rowptr_a[n]);
    int e0 = __ldg(&g_rowptr_a[n + 1]);
    float4 a = row_reduce(g_sorted_a, s0, e0, q, ue, ie);

    int s1 = __ldg(&g_rowptr_r[n]);
    int e1 = __ldg(&g_rowptr_r[n + 1]);
    float4 r = row_reduce(g_sorted_r, s1, e1, q, ue, ie);

    size_t sbase = (size_t)N_CNT * DIM + (size_t)n * 4 * DIM;
    size_t pbase = sbase + (size_t)N_CNT * 4 * DIM;
    float4* s = reinterpret_cast<float4*>(out + sbase);
    float4* p = reinterpret_cast<float4*>(out + pbase);
    __stcs(&s[q],      e);    // stacked slot 0
    __stcs(&s[16 + q], a);    // slots 1..3 identical (reference never updates ego)
    __stcs(&s[32 + q], a);
    __stcs(&s[48 + q], a);
    __stcs(&p[q],      e);
    __stcs(&p[16 + q], r);
    __stcs(&p[32 + q], r);
    __stcs(&p[48 + q], r);

    float4 m = make_float4((e.x + 3.f * a.x) * 0.25f,
                           (e.y + 3.f * a.y) * 0.25f,
                           (e.z + 3.f * a.z) * 0.25f,
                           (e.w + 3.f * a.w) * 0.25f);
    __stcs(&reinterpret_cast<float4*>(out)[(size_t)n * 16 + q], m);
}

extern "C" void kernel_launch(void* const* d_in, const int* in_sizes, int n_in,
                              void* d_out, int out_size) {
    const float* ue     = (const float*)d_in[0];
    const float* ie     = (const float*)d_in[1];
    const int*   a_rows = (const int*)  d_in[2];
    const int*   a_cols = (const int*)  d_in[3];
    const float* a_vals = (const float*)d_in[4];
    const int*   r_rows = (const int*)  d_in[5];
    const int*   r_cols = (const int*)  d_in[6];
    const float* r_vals = (const float*)d_in[7];
    float* out = (float*)d_out;

    lgcn_zero<<<(N_CNT + 255) / 256, 256>>>();
    lgcn_hist<<<(NNZ_E + 255) / 256, 256>>>(a_rows, r_rows);
    lgcn_scan<<<dim3(NBLK, 2), SCAN_B>>>();
    lgcn_scatter<<<(NNZ_E + 255) / 256, 256>>>(a_rows, a_cols, a_vals,
                                               r_rows, r_cols, r_vals);
    lgcn_gather<<<(N_CNT * 16 + 255) / 256, 256>>>(ue, ie, out);
}

// round 9
// speedup vs baseline: 1.0399x; 1.0399x over previous
#include <cuda_runtime.h>
#include <cstdint>

#define U_CNT 100000
#define I_CNT 50000
#define DIM   64
#define N_CNT 150000
#define NNZ_E 1000000

#define SCAN_B 1024
#define NBLK   ((N_CNT + SCAN_B - 1) / SCAN_B)   // 147

// ---- static device scratch (no runtime allocation; zero-init at load) ----
__device__ int  g_cnt_a[N_CNT];           // per-row counts; scan resets to 0 each replay
__device__ int  g_cnt_r[N_CNT];
__device__ int  g_rowptr_a[N_CNT + 1];    // exclusive prefix (scan output)
__device__ int  g_rowptr_r[N_CNT + 1];
__device__ int  g_rank_a[NNZ_E];          // edge rank within its row (from hist)
__device__ int  g_rank_r[NNZ_E];
__device__ unsigned int g_tile_a[NBLK];   // decoupled-lookback: (value<<2)|status
__device__ unsigned int g_tile_r[NBLK];   // status: 0 invalid, 1 aggregate, 2 prefix
__device__ int2 g_sorted_a[NNZ_E];        // (col, val bits) grouped by row
__device__ int2 g_sorted_r[NNZ_E];

static __device__ __forceinline__ const float4* ego_row(
    const float* __restrict__ ue, const float* __restrict__ ie, int n) {
    return (n < U_CNT)
        ? reinterpret_cast<const float4*>(ue + (size_t)n * DIM)
        : reinterpret_cast<const float4*>(ie + (size_t)(n - U_CNT) * DIM);
}

static __device__ __forceinline__ void fma4(float4& acc, float v, const float4& x) {
    acc.x = fmaf(v, x.x, acc.x);
    acc.y = fmaf(v, x.y, acc.y);
    acc.z = fmaf(v, x.z, acc.z);
    acc.w = fmaf(v, x.w, acc.w);
}

// K1: row histogram; atomic return value IS the edge's rank within its row.
// Also re-zeroes the lookback status arrays for the scan that follows
// (counts start at 0: zero-init on first call, reset by scan on later replays).
__global__ void lgcn_hist(const int* __restrict__ a_rows,
                          const int* __restrict__ r_rows) {
    int i = blockIdx.x * blockDim.x + threadIdx.x;
    if (i < NBLK) { g_tile_a[i] = 0u; g_tile_r[i] = 0u; }
    if (i < NNZ_E) {
        g_rank_a[i] = atomicAdd(&g_cnt_a[__ldg(&a_rows[i])], 1);
        g_rank_r[i] = atomicAdd(&g_cnt_r[__ldg(&r_rows[i])], 1);
    }
}

// K2: single-pass exclusive scan (decoupled lookback). Reads counts, RESETS
// them to zero for the next replay, writes prefix to g_rowptr. grid=(NBLK,2).
__global__ void lgcn_scan() {
    int  m = blockIdx.y;
    int  b = blockIdx.x;
    int  t = threadIdx.x;
    int* cnt = m ? g_cnt_r    : g_cnt_a;
    int* ps  = m ? g_rowptr_r : g_rowptr_a;
    unsigned int* st = m ? g_tile_r : g_tile_a;

    __shared__ int s[SCAN_B];
    __shared__ int ex_prefix;

    int i = b * SCAN_B + t;
    int v = (i < N_CNT) ? cnt[i] : 0;
    if (i < N_CNT) cnt[i] = 0;             // self-reset for next replay
    s[t] = v;
    __syncthreads();
    #pragma unroll
    for (int off = 1; off < SCAN_B; off <<= 1) {
        int u = (t >= off) ? s[t - off] : 0;
        __syncthreads();
        s[t] += u;
        __syncthreads();
    }
    int incl  = s[t];
    int total = s[SCAN_B - 1];

    if (t == 0) {
        if (b == 0) {
            ex_prefix = 0;
            atomicExch(&st[0], ((unsigned int)total << 2) | 2u);
        } else {
            atomicExch(&st[b], ((unsigned int)total << 2) | 1u);
            int run = 0;
            for (int j = b - 1; j >= 0; j--) {
                unsigned int x;
                do { x = atomicAdd(&st[j], 0u); } while ((x & 3u) == 0u);
                run += (int)(x >> 2);
                if ((x & 3u) == 2u) break;
            }
            ex_prefix = run;
            atomicExch(&st[b], ((unsigned int)(run + total) << 2) | 2u);
        }
    }
    __syncthreads();

    if (i < N_CNT) ps[i] = ex_prefix + incl - v;   // global exclusive prefix
    if (b == NBLK - 1 && t == SCAN_B - 1) ps[N_CNT] = NNZ_E;
}

// K3: atomic-free scatter — position = rowptr[row] + rank (rank from hist).
__global__ void lgcn_scatter(const int*  __restrict__ a_rows,
                             const int*  __restrict__ a_cols,
                             const float* __restrict__ a_vals,
                             const int*  __restrict__ r_rows,
                             const int*  __restrict__ r_cols,
                             const float* __restrict__ r_vals) {
    int i = blockIdx.x * blockDim.x + threadIdx.x;
    if (i >= NNZ_E) return;
    {
        int row = __ldg(&a_rows[i]);
        int pos = __ldg(&g_rowptr_a[row]) + g_rank_a[i];
        g_sorted_a[pos] = make_int2(__ldg(&a_cols[i]),
                                    __float_as_int(__ldg(&a_vals[i])));
    }
    {
        int row = __ldg(&r_rows[i]);
        int pos = __ldg(&g_rowptr_r[row]) + g_rank_r[i];
        g_sorted_r[pos] = make_int2(__ldg(&r_cols[i]),
                                    __float_as_int(__ldg(&r_vals[i])));
    }
}

// Unroll-4 CSR row reduction with batched independent loads (R4/R7 winner).
static __device__ __forceinline__ float4 row_reduce(
    const int2* __restrict__ sorted, int s, int e, int q,
    const float* __restrict__ ue, const float* __restrict__ ie) {
    float4 acc = make_float4(0.f, 0.f, 0.f, 0.f);
    int i = s;
    for (; i + 4 <= e; i += 4) {
        int2 c0 = __ldg(&sorted[i]);
        int2 c1 = __ldg(&sorted[i + 1]);
        int2 c2 = __ldg(&sorted[i + 2]);
        int2 c3 = __ldg(&sorted[i + 3]);
        float4 x0 = __ldg(&ego_row(ue, ie, c0.x)[q]);
        float4 x1 = __ldg(&ego_row(ue, ie, c1.x)[q]);
        float4 x2 = __ldg(&ego_row(ue, ie, c2.x)[q]);
        float4 x3 = __ldg(&ego_row(ue, ie, c3.x)[q]);
        fma4(acc, __int_as_float(c0.y), x0);
        fma4(acc, __int_as_float(c1.y), x1);
        fma4(acc, __int_as_float(c2.y), x2);
        fma4(acc, __int_as_float(c3.y), x3);
    }
    if (i < e) {
        int2 c0 = __ldg(&sorted[i]);
        int2 c1 = (i + 1 < e) ? __ldg(&sorted[i + 1]) : make_int2(0, 0);
        int2 c2 = (i + 2 < e) ? __ldg(&sorted[i + 2]) : make_int2(0, 0);
        float4 x0 = __ldg(&ego_row(ue, ie, c0.x)[q]);
        fma4(acc, __int_as_float(c0.y), x0);
        if (i + 1 < e) {
            float4 x1 = __ldg(&ego_row(ue, ie, c1.x)[q]);
            fma4(acc, __int_as_float(c1.y), x1);
        }
        if (i + 2 < e) {
            float4 x2 = __ldg(&ego_row(ue, ie, c2.x)[q]);
            fma4(acc, __int_as_float(c2.y), x2);
        }
    }
    return acc;
}

// K4: per-row gather SpMM + full output emit. Streaming stores (never re-read).
__global__ void lgcn_gather(const float* __restrict__ ue,
                            const float* __restrict__ ie,
                            float* __restrict__ out) {
    int idx = blockIdx.x * blockDim.x + threadIdx.x;
    if (idx >= N_CNT * 16) return;
    int n = idx >> 4;
    int q = idx & 15;

    float4 e = __ldg(&ego_row(ue, ie, n)[q]);

    int s0 = __ldg(&g_rowptr_a[n]);
    int e0 = __ldg(&g_rowptr_a[n + 1]);
    float4 a = row_reduce(g_sorted_a, s0, e0, q, ue, ie);

    int s1 = __ldg(&g_rowptr_r[n]);
    int e1 = __ldg(&g_rowptr_r[n + 1]);
    float4 r = row_reduce(g_sorted_r, s1, e1, q, ue, ie);

    size_t sbase = (size_t)N_CNT * DIM + (size_t)n * 4 * DIM;
    size_t pbase = sbase + (size_t)N_CNT * 4 * DIM;
    float4* s = reinterpret_cast<float4*>(out + sbase);
    float4* p = reinterpret_cast<float4*>(out + pbase);
    __stcs(&s[q],      e);    // stacked slot 0
    __stcs(&s[16 + q], a);    // slots 1..3 identical (reference never updates ego)
    __stcs(&s[32 + q], a);
    __stcs(&s[48 + q], a);
    __stcs(&p[q],      e);
    __stcs(&p[16 + q], r);
    __stcs(&p[32 + q], r);
    __stcs(&p[48 + q], r);

    float4 m = make_float4((e.x + 3.f * a.x) * 0.25f,
                           (e.y + 3.f * a.y) * 0.25f,
                           (e.z + 3.f * a.z) * 0.25f,
                           (e.w + 3.f * a.w) * 0.25f);
    __stcs(&reinterpret_cast<float4*>(out)[(size_t)n * 16 + q], m);
}

extern "C" void kernel_launch(void* const* d_in, const int* in_sizes, int n_in,
                              void* d_out, int out_size) {
    const float* ue     = (const float*)d_in[0];
    const float* ie     = (const float*)d_in[1];
    const int*   a_rows = (const int*)  d_in[2];
    const int*   a_cols = (const int*)  d_in[3];
    const float* a_vals = (const float*)d_in[4];
    const int*   r_rows = (const int*)  d_in[5];
    const int*   r_cols = (const int*)  d_in[6];
    const float* r_vals = (const float*)d_in[7];
    float* out = (float*)d_out;

    lgcn_hist<<<(NNZ_E + 255) / 256, 256>>>(a_rows, r_rows);
    lgcn_scan<<<dim3(NBLK, 2), SCAN_B>>>();
    lgcn_scatter<<<(NNZ_E + 255) / 256, 256>>>(a_rows, a_cols, a_vals,
                                               r_rows, r_cols, r_vals);
    lgcn_gather<<<(N_CNT * 16 + 255) / 256, 256>>>(ue, ie, out);
}

// round 10
// speedup vs baseline: 1.0985x; 1.0564x over previous
#include <cuda_runtime.h>
#include <cstdint>

#define U_CNT 100000
#define I_CNT 50000
#define DIM   64
#define N_CNT 150000
#define NNZ_E 1000000

#define SCAN_B 1024
#define NBLK   ((N_CNT + SCAN_B - 1) / SCAN_B)   // 147

// ---- static device scratch (no runtime allocation; zero-init at load) ----
__device__ int  g_cnt_a[N_CNT];           // per-row counts; scan resets to 0 each replay
__device__ int  g_cnt_r[N_CNT];
__device__ int  g_rowptr_a[N_CNT + 1];    // exclusive prefix (scan output)
__device__ int  g_rowptr_r[N_CNT + 1];
__device__ int  g_rank_a[NNZ_E];          // edge rank within its row (from hist)
__device__ int  g_rank_r[NNZ_E];
__device__ unsigned int g_tile_a[NBLK];   // decoupled-lookback: (value<<2)|status
__device__ unsigned int g_tile_r[NBLK];   // status: 0 invalid, 1 aggregate, 2 prefix
__device__ int2 g_sorted_a[NNZ_E];        // (col, val bits) grouped by row
__device__ int2 g_sorted_r[NNZ_E];

static __device__ __forceinline__ const float4* ego_row(
    const float* __restrict__ ue, const float* __restrict__ ie, int n) {
    return (n < U_CNT)
        ? reinterpret_cast<const float4*>(ue + (size_t)n * DIM)
        : reinterpret_cast<const float4*>(ie + (size_t)(n - U_CNT) * DIM);
}

static __device__ __forceinline__ void fma4(float4& acc, float v, const float4& x) {
    acc.x = fmaf(v, x.x, acc.x);
    acc.y = fmaf(v, x.y, acc.y);
    acc.z = fmaf(v, x.z, acc.z);
    acc.w = fmaf(v, x.w, acc.w);
}

// K1: row histogram; atomic return value IS the edge's rank within its row.
// Also re-zeroes the lookback status arrays for the scan that follows.
__global__ void lgcn_hist(const int* __restrict__ a_rows,
                          const int* __restrict__ r_rows) {
    int i = blockIdx.x * blockDim.x + threadIdx.x;
    if (i < NBLK) { g_tile_a[i] = 0u; g_tile_r[i] = 0u; }
    if (i < NNZ_E) {
        g_rank_a[i] = atomicAdd(&g_cnt_a[__ldg(&a_rows[i])], 1);
        g_rank_r[i] = atomicAdd(&g_cnt_r[__ldg(&r_rows[i])], 1);
    }
}

// K2: single-pass exclusive scan (decoupled lookback). Reads counts, RESETS
// them to zero for the next replay, writes prefix to g_rowptr. grid=(NBLK,2).
__global__ void lgcn_scan() {
    int  m = blockIdx.y;
    int  b = blockIdx.x;
    int  t = threadIdx.x;
    int* cnt = m ? g_cnt_r    : g_cnt_a;
    int* ps  = m ? g_rowptr_r : g_rowptr_a;
    unsigned int* st = m ? g_tile_r : g_tile_a;

    __shared__ int s[SCAN_B];
    __shared__ int ex_prefix;

    int i = b * SCAN_B + t;
    int v = (i < N_CNT) ? cnt[i] : 0;
    if (i < N_CNT) cnt[i] = 0;             // self-reset for next replay
    s[t] = v;
    __syncthreads();
    #pragma unroll
    for (int off = 1; off < SCAN_B; off <<= 1) {
        int u = (t >= off) ? s[t - off] : 0;
        __syncthreads();
        s[t] += u;
        __syncthreads();
    }
    int incl  = s[t];
    int total = s[SCAN_B - 1];

    if (t == 0) {
        if (b == 0) {
            ex_prefix = 0;
            atomicExch(&st[0], ((unsigned int)total << 2) | 2u);
        } else {
            atomicExch(&st[b], ((unsigned int)total << 2) | 1u);
            int run = 0;
            for (int j = b - 1; j >= 0; j--) {
                unsigned int x;
                do { x = atomicAdd(&st[j], 0u); } while ((x & 3u) == 0u);
                run += (int)(x >> 2);
                if ((x & 3u) == 2u) break;
            }
            ex_prefix = run;
            atomicExch(&st[b], ((unsigned int)(run + total) << 2) | 2u);
        }
    }
    __syncthreads();

    if (i < N_CNT) ps[i] = ex_prefix + incl - v;   // global exclusive prefix
    if (b == NBLK - 1 && t == SCAN_B - 1) ps[N_CNT] = NNZ_E;
}

// K3: atomic-free scatter — position = rowptr[row] + rank (rank from hist).
__global__ void lgcn_scatter(const int*  __restrict__ a_rows,
                             const int*  __restrict__ a_cols,
                             const float* __restrict__ a_vals,
                             const int*  __restrict__ r_rows,
                             const int*  __restrict__ r_cols,
                             const float* __restrict__ r_vals) {
    int i = blockIdx.x * blockDim.x + threadIdx.x;
    if (i >= NNZ_E) return;
    {
        int row = __ldg(&a_rows[i]);
        int pos = __ldg(&g_rowptr_a[row]) + g_rank_a[i];
        g_sorted_a[pos] = make_int2(__ldg(&a_cols[i]),
                                    __float_as_int(__ldg(&a_vals[i])));
    }
    {
        int row = __ldg(&r_rows[i]);
        int pos = __ldg(&g_rowptr_r[row]) + g_rank_r[i];
        g_sorted_r[pos] = make_int2(__ldg(&r_cols[i]),
                                    __float_as_int(__ldg(&r_vals[i])));
    }
}

// Unroll-4 CSR row reduction with batched independent loads (R4/R7 winner).
static __device__ __forceinline__ float4 row_reduce(
    const int2* __restrict__ sorted, int s, int e, int q,
    const float* __restrict__ ue, const float* __restrict__ ie) {
    float4 acc = make_float4(0.f, 0.f, 0.f, 0.f);
    int i = s;
    for (; i + 4 <= e; i += 4) {
        int2 c0 = __ldg(&sorted[i]);
        int2 c1 = __ldg(&sorted[i + 1]);
        int2 c2 = __ldg(&sorted[i + 2]);
        int2 c3 = __ldg(&sorted[i + 3]);
        float4 x0 = __ldg(&ego_row(ue, ie, c0.x)[q]);
        float4 x1 = __ldg(&ego_row(ue, ie, c1.x)[q]);
        float4 x2 = __ldg(&ego_row(ue, ie, c2.x)[q]);
        float4 x3 = __ldg(&ego_row(ue, ie, c3.x)[q]);
        fma4(acc, __int_as_float(c0.y), x0);
        fma4(acc, __int_as_float(c1.y), x1);
        fma4(acc, __int_as_float(c2.y), x2);
        fma4(acc, __int_as_float(c3.y), x3);
    }
    if (i < e) {
        int2 c0 = __ldg(&sorted[i]);
        int2 c1 = (i + 1 < e) ? __ldg(&sorted[i + 1]) : make_int2(0, 0);
        int2 c2 = (i + 2 < e) ? __ldg(&sorted[i + 2]) : make_int2(0, 0);
        float4 x0 = __ldg(&ego_row(ue, ie, c0.x)[q]);
        fma4(acc, __int_as_float(c0.y), x0);
        if (i + 1 < e) {
            float4 x1 = __ldg(&ego_row(ue, ie, c1.x)[q]);
            fma4(acc, __int_as_float(c1.y), x1);
        }
        if (i + 2 < e) {
            float4 x2 = __ldg(&ego_row(ue, ie, c2.x)[q]);
            fma4(acc, __int_as_float(c2.y), x2);
        }
    }
    return acc;
}

// K4: per-row gather SpMM + full output emit. Streaming stores (never re-read).
// __launch_bounds__(256, 8): cap regs at 32 -> 2048 threads/SM (100% occ) to
// hide the rowptr->sorted->ego dependent-load latency.
__global__ void __launch_bounds__(256, 8)
lgcn_gather(const float* __restrict__ ue,
            const float* __restrict__ ie,
            float* __restrict__ out) {
    int idx = blockIdx.x * blockDim.x + threadIdx.x;
    if (idx >= N_CNT * 16) return;
    int n = idx >> 4;
    int q = idx & 15;

    // front-load all independent scalars: both rowptr pairs + ego self-row
    int s0 = __ldg(&g_rowptr_a[n]);
    int e0 = __ldg(&g_rowptr_a[n + 1]);
    int s1 = __ldg(&g_rowptr_r[n]);
    int e1 = __ldg(&g_rowptr_r[n + 1]);
    float4 e = __ldg(&ego_row(ue, ie, n)[q]);

    float4 a = row_reduce(g_sorted_a, s0, e0, q, ue, ie);
    float4 r = row_reduce(g_sorted_r, s1, e1, q, ue, ie);

    size_t sbase = (size_t)N_CNT * DIM + (size_t)n * 4 * DIM;
    size_t pbase = sbase + (size_t)N_CNT * 4 * DIM;
    float4* s = reinterpret_cast<float4*>(out + sbase);
    float4* p = reinterpret_cast<float4*>(out + pbase);
    __stcs(&s[q],      e);    // stacked slot 0
    __stcs(&s[16 + q], a);    // slots 1..3 identical (reference never updates ego)
    __stcs(&s[32 + q], a);
    __stcs(&s[48 + q], a);
    __stcs(&p[q],      e);
    __stcs(&p[16 + q], r);
    __stcs(&p[32 + q], r);
    __stcs(&p[48 + q], r);

    float4 m = make_float4((e.x + 3.f * a.x) * 0.25f,
                           (e.y + 3.f * a.y) * 0.25f,
                           (e.z + 3.f * a.z) * 0.25f,
                           (e.w + 3.f * a.w) * 0.25f);
    __stcs(&reinterpret_cast<float4*>(out)[(size_t)n * 16 + q], m);
}

extern "C" void kernel_launch(void* const* d_in, const int* in_sizes, int n_in,
                              void* d_out, int out_size) {
    const float* ue     = (const float*)d_in[0];
    const float* ie     = (const float*)d_in[1];
    const int*   a_rows = (const int*)  d_in[2];
    const int*   a_cols = (const int*)  d_in[3];
    const float* a_vals = (const float*)d_in[4];
    const int*   r_rows = (const int*)  d_in[5];
    const int*   r_cols = (const int*)  d_in[6];
    const float* r_vals = (const float*)d_in[7];
    float* out = (float*)d_out;

    lgcn_hist<<<(NNZ_E + 255) / 256, 256>>>(a_rows, r_rows);
    lgcn_scan<<<dim3(NBLK, 2), SCAN_B>>>();
    lgcn_scatter<<<(NNZ_E + 255) / 256, 256>>>(a_rows, a_cols, a_vals,
                                               r_rows, r_cols, r_vals);
    lgcn_gather<<<(N_CNT * 16 + 255) / 256, 256>>>(ue, ie, out);
}

// round 11
// speedup vs baseline: 1.1262x; 1.0252x over previous
#include <cuda_runtime.h>
#include <cstdint>

#define U_CNT 100000
#define I_CNT 50000
#define DIM   64
#define N_CNT 150000
#define NNZ_E 1000000
#define NNZ_T (2 * NNZ_E)                 // combined edge count

#define SCAN_B 1024
#define NBLK   ((N_CNT + SCAN_B - 1) / SCAN_B)   // 147

// ---- static device scratch (no runtime allocation; zero-init at load) ----
__device__ int  g_cnt_a[N_CNT];           // per-row counts; scan resets to 0 each replay
__device__ int  g_cnt_r[N_CNT];
__device__ int  g_rowptr[N_CNT + 1];      // combined exclusive prefix (A+R per row)
__device__ int  g_mid[N_CNT];             // rowptr[n] + degA[n]  (A|R boundary)
__device__ int  g_rank_a[NNZ_E];          // edge rank within its row (from hist)
__device__ int  g_rank_r[NNZ_E];
__device__ unsigned int g_tile[NBLK];     // decoupled-lookback: (value<<2)|status
__device__ int2 g_sorted[NNZ_T];          // (col, val bits); per row: A edges then R edges

static __device__ __forceinline__ const float4* ego_row(
    const float* __restrict__ ue, const float* __restrict__ ie, int n) {
    return (n < U_CNT)
        ? reinterpret_cast<const float4*>(ue + (size_t)n * DIM)
        : reinterpret_cast<const float4*>(ie + (size_t)(n - U_CNT) * DIM);
}

static __device__ __forceinline__ void fma4(float4& acc, float v, const float4& x) {
    acc.x = fmaf(v, x.x, acc.x);
    acc.y = fmaf(v, x.y, acc.y);
    acc.z = fmaf(v, x.z, acc.z);
    acc.w = fmaf(v, x.w, acc.w);
}

// K1: row histogram; atomic return value IS the edge's rank within its row.
// Also re-zeroes the lookback status array for the scan that follows.
__global__ void lgcn_hist(const int* __restrict__ a_rows,
                          const int* __restrict__ r_rows) {
    int i = blockIdx.x * blockDim.x + threadIdx.x;
    if (i < NBLK) g_tile[i] = 0u;
    if (i < NNZ_E) {
        g_rank_a[i] = atomicAdd(&g_cnt_a[__ldg(&a_rows[i])], 1);
        g_rank_r[i] = atomicAdd(&g_cnt_r[__ldg(&r_rows[i])], 1);
    }
}

// K2: single-pass exclusive scan over combined degrees (decoupled lookback).
// Reads both counts, RESETS them, writes combined rowptr and the A|R midpoint.
__global__ void lgcn_scan() {
    int b = blockIdx.x;
    int t = threadIdx.x;

    __shared__ int s[SCAN_B];
    __shared__ int ex_prefix;

    int i = b * SCAN_B + t;
    int cA = 0, cR = 0;
    if (i < N_CNT) {
        cA = g_cnt_a[i];
        cR = g_cnt_r[i];
        g_cnt_a[i] = 0;                    // self-reset for next replay
        g_cnt_r[i] = 0;
    }
    int v = cA + cR;
    s[t] = v;
    __syncthreads();
    #pragma unroll
    for (int off = 1; off < SCAN_B; off <<= 1) {
        int u = (t >= off) ? s[t - off] : 0;
        __syncthreads();
        s[t] += u;
        __syncthreads();
    }
    int incl  = s[t];
    int total = s[SCAN_B - 1];

    if (t == 0) {
        if (b == 0) {
            ex_prefix = 0;
            atomicExch(&g_tile[0], ((unsigned int)total << 2) | 2u);
        } else {
            atomicExch(&g_tile[b], ((unsigned int)total << 2) | 1u);
            int run = 0;
            for (int j = b - 1; j >= 0; j--) {
                unsigned int x;
                do { x = atomicAdd(&g_tile[j], 0u); } while ((x & 3u) == 0u);
                run += (int)(x >> 2);
                if ((x & 3u) == 2u) break;
            }
            ex_prefix = run;
            atomicExch(&g_tile[b], ((unsigned int)(run + total) << 2) | 2u);
        }
    }
    __syncthreads();

    if (i < N_CNT) {
        int pref = ex_prefix + incl - v;   // combined exclusive prefix
        g_rowptr[i] = pref;
        g_mid[i]    = pref + cA;
    }
    if (b == NBLK - 1 && t == SCAN_B - 1) g_rowptr[N_CNT] = NNZ_T;
}

// K3: atomic-free scatter into the combined layout.
// A edge -> rowptr[row] + rank_a ; R edge -> mid[row] + rank_r.
__global__ void lgcn_scatter(const int*  __restrict__ a_rows,
                             const int*  __restrict__ a_cols,
                             const float* __restrict__ a_vals,
                             const int*  __restrict__ r_rows,
                             const int*  __restrict__ r_cols,
                             const float* __restrict__ r_vals) {
    int i = blockIdx.x * blockDim.x + threadIdx.x;
    if (i >= NNZ_E) return;
    {
        int row = __ldg(&a_rows[i]);
        int pos = __ldg(&g_rowptr[row]) + g_rank_a[i];
        g_sorted[pos] = make_int2(__ldg(&a_cols[i]),
                                  __float_as_int(__ldg(&a_vals[i])));
    }
    {
        int row = __ldg(&r_rows[i]);
        int pos = __ldg(&g_mid[row]) + g_rank_r[i];
        g_sorted[pos] = make_int2(__ldg(&r_cols[i]),
                                  __float_as_int(__ldg(&r_vals[i])));
    }
}

// K4: per-row gather SpMM + full output emit. ONE loop over the combined
// segment; accumulator selected by predicated compare against mid.
__global__ void __launch_bounds__(256, 8)
lgcn_gather(const float* __restrict__ ue,
            const float* __restrict__ ie,
            float* __restrict__ out) {
    int idx = blockIdx.x * blockDim.x + threadIdx.x;
    if (idx >= N_CNT * 16) return;
    int n = idx >> 4;
    int q = idx & 15;

    int s0  = __ldg(&g_rowptr[n]);
    int e0  = __ldg(&g_rowptr[n + 1]);
    int mid = __ldg(&g_mid[n]);

    // prefetch the row's edge records while the ego self-load is in flight
    asm volatile("prefetch.global.L1 [%0];" :: "l"(g_sorted + s0));
    asm volatile("prefetch.global.L1 [%0];" :: "l"(g_sorted + (e0 - 1)));

    float4 e = __ldg(&ego_row(ue, ie, n)[q]);

    float4 a = make_float4(0.f, 0.f, 0.f, 0.f);
    float4 r = make_float4(0.f, 0.f, 0.f, 0.f);

    int i = s0;
    for (; i + 4 <= e0; i += 4) {
        int2 c0 = __ldg(&g_sorted[i]);
        int2 c1 = __ldg(&g_sorted[i + 1]);
        int2 c2 = __ldg(&g_sorted[i + 2]);
        int2 c3 = __ldg(&g_sorted[i + 3]);
        float4 x0 = __ldg(&ego_row(ue, ie, c0.x)[q]);
        float4 x1 = __ldg(&ego_row(ue, ie, c1.x)[q]);
        float4 x2 = __ldg(&ego_row(ue, ie, c2.x)[q]);
        float4 x3 = __ldg(&ego_row(ue, ie, c3.x)[q]);
        if (i     < mid) fma4(a, __int_as_float(c0.y), x0); else fma4(r, __int_as_float(c0.y), x0);
        if (i + 1 < mid) fma4(a, __int_as_float(c1.y), x1); else fma4(r, __int_as_float(c1.y), x1);
        if (i + 2 < mid) fma4(a, __int_as_float(c2.y), x2); else fma4(r, __int_as_float(c2.y), x2);
        if (i + 3 < mid) fma4(a, __int_as_float(c3.y), x3); else fma4(r, __int_as_float(c3.y), x3);
    }
    if (i < e0) {
        int2 c0 = __ldg(&g_sorted[i]);
        int2 c1 = (i + 1 < e0) ? __ldg(&g_sorted[i + 1]) : make_int2(0, 0);
        int2 c2 = (i + 2 < e0) ? __ldg(&g_sorted[i + 2]) : make_int2(0, 0);
        float4 x0 = __ldg(&ego_row(ue, ie, c0.x)[q]);
        if (i < mid) fma4(a, __int_as_float(c0.y), x0); else fma4(r, __int_as_float(c0.y), x0);
        if (i + 1 < e0) {
            float4 x1 = __ldg(&ego_row(ue, ie, c1.x)[q]);
            if (i + 1 < mid) fma4(a, __int_as_float(c1.y), x1); else fma4(r, __int_as_float(c1.y), x1);
        }
        if (i + 2 < e0) {
            float4 x2 = __ldg(&ego_row(ue, ie, c2.x)[q]);
            if (i + 2 < mid) fma4(a, __int_as_float(c2.y), x2); else fma4(r, __int_as_float(c2.y), x2);
        }
    }

    size_t sbase = (size_t)N_CNT * DIM + (size_t)n * 4 * DIM;
    size_t pbase = sbase + (size_t)N_CNT * 4 * DIM;
    float4* s = reinterpret_cast<float4*>(out + sbase);
    float4* p = reinterpret_cast<float4*>(out + pbase);
    __stcs(&s[q],      e);    // stacked slot 0
    __stcs(&s[16 + q], a);    // slots 1..3 identical (reference never updates ego)
    __stcs(&s[32 + q], a);
    __stcs(&s[48 + q], a);
    __stcs(&p[q],      e);
    __stcs(&p[16 + q], r);
    __stcs(&p[32 + q], r);
    __stcs(&p[48 + q], r);

    float4 m = make_float4((e.x + 3.f * a.x) * 0.25f,
                           (e.y + 3.f * a.y) * 0.25f,
                           (e.z + 3.f * a.z) * 0.25f,
                           (e.w + 3.f * a.w) * 0.25f);
    __stcs(&reinterpret_cast<float4*>(out)[(size_t)n * 16 + q], m);
}

extern "C" void kernel_launch(void* const* d_in, const int* in_sizes, int n_in,
                              void* d_out, int out_size) {
    const float* ue     = (const float*)d_in[0];
    const float* ie     = (const float*)d_in[1];
    const int*   a_rows = (const int*)  d_in[2];
    const int*   a_cols = (const int*)  d_in[3];
    const float* a_vals = (const float*)d_in[4];
    const int*   r_rows = (const int*)  d_in[5];
    const int*   r_cols = (const int*)  d_in[6];
    const float* r_vals = (const float*)d_in[7];
    float* out = (float*)d_out;

    lgcn_hist<<<(NNZ_E + 255) / 256, 256>>>(a_rows, r_rows);
    lgcn_scan<<<NBLK, SCAN_B>>>();
    lgcn_scatter<<<(NNZ_E + 255) / 256, 256>>>(a_rows, a_cols, a_vals,
                                               r_rows, r_cols, r_vals);
    lgcn_gather<<<(N_CNT * 16 + 255) / 256, 256>>>(ue, ie, out);
}